// round 7
// baseline (speedup 1.0000x reference)
#include <cuda_runtime.h>
#include <cuda_bf16.h>

// Problem shape (fixed by the reference)
#define BB 16
#define TT 4096
#define HH 512
#define H4 (HH / 4)      // 128 float4 per row
#define LANES 8          // float4 lanes per CTA -> 32 float columns
#define SLICES (H4 / LANES)   // 16 column-slices per batch
#define THREADS 256
#define TROWS (THREADS / LANES)  // 32 t-rows walked concurrently

// Single kernel: CTA = (batch, 32-column slice). Walks all T=4096 rows,
// accumulating both the length-masked (global) and mask-selected (local)
// sums for its slice, then tree-reduces in smem and writes out directly.
// No scratch, no atomics, no second kernel.
__global__ __launch_bounds__(THREADS) void pool_kernel(
    const float4* __restrict__ x,
    const int* __restrict__ lengths,
    const int* __restrict__ mask,        // jax bool materialized as int32
    float* __restrict__ out)
{
    const int b     = blockIdx.x / SLICES;
    const int slice = blockIdx.x % SLICES;
    const int tid   = threadIdx.x;
    const int lane  = tid % LANES;       // which float4 column
    const int trow  = tid / LANES;       // 0..31, starting t offset

    const int L = lengths[b];

    const float4* __restrict__ xp =
        x + (size_t)b * TT * H4 + (size_t)slice * LANES + lane;
    const int* __restrict__ mp = mask + (size_t)b * TT;

    float4 ag = make_float4(0.f, 0.f, 0.f, 0.f);
    float4 al = make_float4(0.f, 0.f, 0.f, 0.f);
    int cnt = 0;

    // 128 iterations per thread; unroll 8 for deep MLP.
    #pragma unroll 8
    for (int t = trow; t < TT; t += TROWS) {
        float4 v = __ldcs(&xp[(size_t)t * H4]);
        bool g = t < L;
        bool m = (mp[t] != 0);           // 8-way broadcast within warp
        if (g) { ag.x += v.x; ag.y += v.y; ag.z += v.z; ag.w += v.w; }
        if (m) { al.x += v.x; al.y += v.y; al.z += v.z; al.w += v.w; cnt++; }
    }

    // Tree-reduce across the 32 t-rows (same lane).
    __shared__ float4 s_g[THREADS];
    __shared__ float4 s_l[THREADS];
    __shared__ int    s_c[THREADS];
    s_g[tid] = ag; s_l[tid] = al; s_c[tid] = cnt;
    __syncthreads();

    #pragma unroll
    for (int st = TROWS / 2; st >= 1; st >>= 1) {
        if (trow < st) {
            const int o = tid + st * LANES;
            float4 a = s_g[o], d = s_l[o];
            float4 sg = s_g[tid], sl = s_l[tid];
            sg.x += a.x; sg.y += a.y; sg.z += a.z; sg.w += a.w;
            sl.x += d.x; sl.y += d.y; sl.z += d.z; sl.w += d.w;
            s_g[tid] = sg; s_l[tid] = sl;
            s_c[tid] += s_c[o];
        }
        __syncthreads();
    }

    if (trow == 0) {
        const float dg = 1.0f / (float)(L > 1 ? L : 1);
        const int tot = s_c[lane];       // full count over all T for this CTA
        const float dl = 1.0f / (float)(tot > 1 ? tot : 1);

        float4 sg = s_g[lane], sl = s_l[lane];
        float4* o4 = reinterpret_cast<float4*>(out)
                   + (size_t)b * (2 * HH / 4) + slice * LANES + lane;
        o4[0]  = make_float4(sg.x * dg, sg.y * dg, sg.z * dg, sg.w * dg);
        o4[H4] = make_float4(sl.x * dl, sl.y * dl, sl.z * dl, sl.w * dl);
    }
}

extern "C" void kernel_launch(void* const* d_in, const int* in_sizes, int n_in,
                              void* d_out, int out_size)
{
    const float4* x       = (const float4*)d_in[0];   // [B,T,H] f32
    const int*    lengths = (const int*)d_in[1];      // [B] i32
    const int*    mask    = (const int*)d_in[2];      // [B,T] bool -> i32
    float*        out     = (float*)d_out;            // [B, 2H] f32

    pool_kernel<<<BB * SLICES, THREADS>>>(x, lengths, mask, out);
}

// round 8
// speedup vs baseline: 1.8253x; 1.8253x over previous
#include <cuda_runtime.h>
#include <cuda_bf16.h>

// Problem shape (fixed by the reference)
#define BB 16
#define TT 4096
#define HH 512
#define SS 64            // T-chunks per batch
#define TC (TT / SS)     // 64 rows per chunk
#define H4 (HH / 4)      // 128 float4 per row
#define CP 4             // pass-2 chunk-splits  (SS/CP = 16 chunks per thread)
#define COLP 8           // pass-2 column-splits (1024 cols / 128 threads)

// Scratch: per (b, chunk): 512 global-sum + 512 local-sum floats (4 MiB)
__device__ float g_partial[BB * SS * 2 * HH];
__device__ int   g_counts[BB * SS];

// Pass 1: each CTA handles one (b, t-chunk); 128 threads x float4 cover H=512.
// Rows with t >= L AND mask==0 contribute nothing and are skipped entirely
// (warp-uniform branch -> the 2 KiB row is never fetched). Expected ~25%
// DRAM traffic reduction. First 32 CTAs also zero the output buffer.
__global__ __launch_bounds__(128) void pass1_kernel(
    const float4* __restrict__ x,
    const int* __restrict__ lengths,
    const int* __restrict__ mask,        // jax bool materialized as int32
    float4* __restrict__ out4)           // [B*2H/4] — zeroed here
{
    const int blk = blockIdx.x;          // 0 .. B*S-1
    const int b   = blk / SS;
    const int s   = blk % SS;
    const int tid = threadIdx.x;         // 0..127

    // Zero out[] (4096 float4) across the first 32 CTAs.
    if (blk < 32) out4[blk * 128 + tid] = make_float4(0.f, 0.f, 0.f, 0.f);

    const int L  = lengths[b];
    const int t0 = s * TC;
    int Lc = L - t0;                     // rows in this chunk with t < L
    Lc = Lc < 0 ? 0 : (Lc > TC ? TC : Lc);

    const float4* __restrict__ xp = x + (size_t)b * TT * H4 + (size_t)t0 * H4 + tid;
    const int* __restrict__ mp = mask + (size_t)b * TT + t0;

    float4 ag = make_float4(0.f, 0.f, 0.f, 0.f);
    float4 al = make_float4(0.f, 0.f, 0.f, 0.f);
    int cnt = 0;

    // Region A: t < Lc — row always needed (global sum), mask gates local.
    int t = 0;
    #pragma unroll 4
    for (; t < Lc; ++t) {
        float4 v = xp[(size_t)t * H4];
        ag.x += v.x; ag.y += v.y; ag.z += v.z; ag.w += v.w;
        if (mp[t] != 0) { al.x += v.x; al.y += v.y; al.z += v.z; al.w += v.w; cnt++; }
    }
    // Region B: t >= Lc — row needed only if masked (skip ~50% of fetches).
    #pragma unroll 4
    for (; t < TC; ++t) {
        if (mp[t] != 0) {
            float4 v = xp[(size_t)t * H4];
            al.x += v.x; al.y += v.y; al.z += v.z; al.w += v.w; cnt++;
        }
    }

    float4* outp = reinterpret_cast<float4*>(g_partial) + (size_t)blk * (2 * HH / 4);
    outp[tid]      = ag;
    outp[H4 + tid] = al;
    if (tid == 0) g_counts[blk] = cnt;
}

// Pass 2: 512 CTAs = (b, colpart, chunkpart); 128 threads. Each thread sums
// 16 chunk-partials for one output column (MLP 16), pre-divides by the
// denominator, and atomically accumulates into out (4 adds per address).
__global__ __launch_bounds__(128) void pass2_kernel(
    const int* __restrict__ lengths,
    float* __restrict__ out)
{
    const int blk       = blockIdx.x;
    const int b         = blk / (COLP * CP);
    const int colpart   = (blk / CP) % COLP;
    const int chunkpart = blk % CP;
    const int h         = colpart * 128 + threadIdx.x;     // 0..1023

    const int c0 = chunkpart * (SS / CP);
    const float* p = g_partial + ((size_t)b * SS + c0) * (2 * HH) + h;

    float sum = 0.f;
    #pragma unroll
    for (int c = 0; c < SS / CP; ++c)
        sum += p[(size_t)c * (2 * HH)];

    float denom;
    if (h < HH) {
        const int L = lengths[b];
        denom = (float)(L > 1 ? L : 1);
    } else {
        int tot = 0;
        #pragma unroll 8
        for (int c = 0; c < SS; ++c) tot += g_counts[b * SS + c];  // L2-hot
        denom = (float)(tot > 1 ? tot : 1);
    }

    atomicAdd(&out[(size_t)b * 2 * HH + h], sum / denom);
}

extern "C" void kernel_launch(void* const* d_in, const int* in_sizes, int n_in,
                              void* d_out, int out_size)
{
    const float4* x       = (const float4*)d_in[0];   // [B,T,H] f32
    const int*    lengths = (const int*)d_in[1];      // [B] i32
    const int*    mask    = (const int*)d_in[2];      // [B,T] bool -> i32
    float*        out     = (float*)d_out;            // [B, 2H] f32

    pass1_kernel<<<BB * SS, 128>>>(x, lengths, mask, (float4*)out);
    pass2_kernel<<<BB * COLP * CP, 128>>>(lengths, out);
}